// round 4
// baseline (speedup 1.0000x reference)
#include <cuda_runtime.h>

// Cost-volume construction:
//   out[0, c,      d, h, w] = imgl[0, c, h, w]                      (broadcast over d)
//   out[0, c + 32, d, h, w] = (w >= d) ? imgr[0, c, h, w - d] : 0
// Shapes: imgl/imgr (1, 32, 256, 480) f32, out (1, 64, 32, 256, 480) f32.
//
// R4 vs R3 (160.9us, DRAM 79.4%, occ 89%): DRAM% has been invariant across
// occupancy 42->89% and store policies -> testing the DRAM-page-locality
// hypothesis. Each thread now covers 8 consecutive floats (2 adjacent
// STG.128), so a warp writes 1KB contiguous per disparity-plane visit
// (vs 512B) and a block covers 8KB contiguous. Read traffic per byte
// stored also halves (1 scalar window load per 32B stored).

constexpr int C  = 32;
constexpr int D  = 32;
constexpr int H2 = 256;
constexpr int W2 = 480;
constexpr int W8 = W2 / 8;              // 60 8-float groups per row
constexpr int PLANE = H2 * W2;          // 122880 floats
constexpr int CH    = D * PLANE;        // 3,932,160 floats per out-channel
constexpr int DSPLIT = 8;               // disparities per thread
constexpr int NSPLIT = D / DSPLIT;      // 4

__global__ __launch_bounds__(256) void cost_volume_kernel(
    const float* __restrict__ imgl,
    const float* __restrict__ imgr,
    float* __restrict__ out)
{
    int idx = blockIdx.x * blockDim.x + threadIdx.x;

    int w8 = idx % W8;
    int t  = idx / W8;
    int h  = t % H2;
    t /= H2;
    int c     = t % C;
    int split = t / C;                  // 0..3
    int w  = w8 * 8;
    int d0 = split * DSPLIT;

    // ---- Left half: broadcast 8 floats across DSPLIT disparity slices ----
    const float* lrow = imgl + c * PLANE + h * W2 + w;
    const float4 l0 = *reinterpret_cast<const float4*>(lrow);
    const float4 l1 = *reinterpret_cast<const float4*>(lrow + 4);

    float* outL = out + c * CH + d0 * PLANE + h * W2 + w;
#pragma unroll
    for (int i = 0; i < DSPLIT; ++i) {
        __stcs(reinterpret_cast<float4*>(outL + i * PLANE), l0);
        __stcs(reinterpret_cast<float4*>(outL + i * PLANE + 4), l1);
    }

    // ---- Right half: sliding 8-float register window over shifted row ----
    const float* rrow = imgr + c * PLANE + h * W2;
    float* outR = out + (c + C) * CH + d0 * PLANE + h * W2 + w;

    // initial window: positions [s, s+7], zero-filled where negative
    int s = w - d0;
    float4 r0, r1;
    r0.x = (s     >= 0) ? rrow[s]     : 0.0f;
    r0.y = (s + 1 >= 0) ? rrow[s + 1] : 0.0f;
    r0.z = (s + 2 >= 0) ? rrow[s + 2] : 0.0f;
    r0.w = (s + 3 >= 0) ? rrow[s + 3] : 0.0f;
    r1.x = (s + 4 >= 0) ? rrow[s + 4] : 0.0f;
    r1.y = (s + 5 >= 0) ? rrow[s + 5] : 0.0f;
    r1.z = (s + 6 >= 0) ? rrow[s + 6] : 0.0f;
    r1.w = (s + 7 >= 0) ? rrow[s + 7] : 0.0f;
    __stcs(reinterpret_cast<float4*>(outR), r0);
    __stcs(reinterpret_cast<float4*>(outR + 4), r1);

#pragma unroll
    for (int i = 1; i < DSPLIT; ++i) {
        // window slides left by one element per disparity step
        r1.w = r1.z;  r1.z = r1.y;  r1.y = r1.x;  r1.x = r0.w;
        r0.w = r0.z;  r0.z = r0.y;  r0.y = r0.x;
        int src = s - i;
        r0.x = (src >= 0) ? __ldg(rrow + src) : 0.0f;
        __stcs(reinterpret_cast<float4*>(outR + i * PLANE), r0);
        __stcs(reinterpret_cast<float4*>(outR + i * PLANE + 4), r1);
    }
}

extern "C" void kernel_launch(void* const* d_in, const int* in_sizes, int n_in,
                              void* d_out, int out_size)
{
    const float* imgl = (const float*)d_in[0];
    const float* imgr = (const float*)d_in[1];
    float* out = (float*)d_out;

    const int total = NSPLIT * C * H2 * W8;          // 1,966,080 threads
    const int block = 256;
    const int grid  = (total + block - 1) / block;   // 7680 blocks
    cost_volume_kernel<<<grid, block>>>(imgl, imgr, out);
}

// round 5
// speedup vs baseline: 1.9301x; 1.9301x over previous
#include <cuda_runtime.h>

// Cost-volume construction:
//   out[0, c,      d, h, w] = imgl[0, c, h, w]                      (broadcast over d)
//   out[0, c + 32, d, h, w] = (w >= d) ? imgr[0, c, h, w - d] : 0
// Shapes: imgl/imgr (1, 32, 256, 480) f32, out (1, 64, 32, 256, 480) f32.
//
// R5: back to R3's fully-coalesced thread-contiguous float4 layout (R4's
// 8-per-thread layout broke warp coalescing: half-written 128B sectors ->
// 2x write cost). Changes vs R3 (160.9us, DRAM 79.4%):
//  - block 256 -> 512: 8KB contiguous block footprint per d-plane visit
//  - left and right halves interleaved in ONE d-loop: each iteration stores
//    to both output regions (~500MB apart) -> two concurrent write streams,
//    more DRAM bank/pseudo-channel parallelism.

constexpr int C  = 32;
constexpr int D  = 32;
constexpr int H2 = 256;
constexpr int W2 = 480;
constexpr int W4 = W2 / 4;              // 120 float4 per row
constexpr int PLANE = H2 * W2;          // 122880 floats
constexpr int CH    = D * PLANE;        // 3,932,160 floats per out-channel
constexpr int DSPLIT = 8;               // disparities per thread
constexpr int NSPLIT = D / DSPLIT;      // 4

__global__ __launch_bounds__(512, 4) void cost_volume_kernel(
    const float* __restrict__ imgl,
    const float* __restrict__ imgr,
    float* __restrict__ out)
{
    int idx = blockIdx.x * blockDim.x + threadIdx.x;

    int w4 = idx % W4;
    int t  = idx / W4;
    int h  = t % H2;
    t /= H2;
    int c     = t % C;
    int split = t / C;                  // 0..3
    int w  = w4 * 4;
    int d0 = split * DSPLIT;

    // ---- Left operand: one float4, broadcast over DSPLIT disparities ----
    const float4 l = *reinterpret_cast<const float4*>(imgl + c * PLANE + h * W2 + w);

    // ---- Right operand: sliding 4-float register window ----
    const float* rrow = imgr + c * PLANE + h * W2;
    int s = w - d0;
    float4 r;
    r.x = (s     >= 0) ? rrow[s]     : 0.0f;
    r.y = (s + 1 >= 0) ? rrow[s + 1] : 0.0f;
    r.z = (s + 2 >= 0) ? rrow[s + 2] : 0.0f;
    r.w = (s + 3 >= 0) ? rrow[s + 3] : 0.0f;

    float* outL = out + c * CH       + d0 * PLANE + h * W2 + w;
    float* outR = out + (c + C) * CH + d0 * PLANE + h * W2 + w;

    // interleaved stores: both write streams active every iteration
    __stcs(reinterpret_cast<float4*>(outL), l);
    __stcs(reinterpret_cast<float4*>(outR), r);

#pragma unroll
    for (int i = 1; i < DSPLIT; ++i) {
        // window slides left by one element per disparity step
        r.w = r.z;
        r.z = r.y;
        r.y = r.x;
        int src = s - i;
        r.x = (src >= 0) ? __ldg(rrow + src) : 0.0f;
        __stcs(reinterpret_cast<float4*>(outL + i * PLANE), l);
        __stcs(reinterpret_cast<float4*>(outR + i * PLANE), r);
    }
}

extern "C" void kernel_launch(void* const* d_in, const int* in_sizes, int n_in,
                              void* d_out, int out_size)
{
    const float* imgl = (const float*)d_in[0];
    const float* imgr = (const float*)d_in[1];
    float* out = (float*)d_out;

    const int total = NSPLIT * C * H2 * W4;          // 3,932,160 threads
    const int block = 512;
    const int grid  = (total + block - 1) / block;   // 7680 blocks
    cost_volume_kernel<<<grid, block>>>(imgl, imgr, out);
}